// round 9
// baseline (speedup 1.0000x reference)
#include <cuda_runtime.h>
#include <cuda_bf16.h>
#include <math.h>
#include <stdint.h>

// Problem constants
#define B_  2
#define N_  2048
#define C_  1024
#define R_  64
#define H_  16
#define DH_ 64
#define M_  (B_ * N_)          // 4096 rows
#define QKV3_ (3 * C_)         // 3072

typedef __nv_bfloat16 bf16;

// Scratch (device globals: allocation-free)
__device__ bf16 g_wqa  [C_ * R_];
__device__ bf16 g_wqb  [R_ * QKV3_];
__device__ bf16 g_wpa  [C_ * R_];
__device__ bf16 g_wpb  [R_ * C_];
__device__ bf16 g_h1   [M_ * R_];
__device__ bf16 g_qkv  [M_ * QKV3_];     // 24 MB
__device__ bf16 g_attn [M_ * C_];        // 8 MB
__device__ bf16 g_h2   [M_ * R_];

__device__ __forceinline__ float gelu_exact(float x) {
    return 0.5f * x * (1.0f + erff(x * 0.70710678118654752f));
}

__device__ __forceinline__ uint32_t pack_bf16(float lo, float hi) {
    uint32_t r;
    asm("cvt.rn.bf16x2.f32 %0, %1, %2;" : "=r"(r) : "f"(hi), "f"(lo));
    return r;
}

__device__ __forceinline__ uint32_t mulbf2(uint32_t a, uint32_t b) {
    uint32_t d;
    asm("mul.bf16x2 %0, %1, %2;" : "=r"(d) : "r"(a), "r"(b));
    return d;
}

__device__ __forceinline__ void mma16816(float* c, const uint32_t* a,
                                         uint32_t b0, uint32_t b1) {
    asm volatile(
        "mma.sync.aligned.m16n8k16.row.col.f32.bf16.bf16.f32 "
        "{%0,%1,%2,%3}, {%4,%5,%6,%7}, {%8,%9}, {%0,%1,%2,%3};"
        : "+f"(c[0]), "+f"(c[1]), "+f"(c[2]), "+f"(c[3])
        : "r"(a[0]), "r"(a[1]), "r"(a[2]), "r"(a[3]), "r"(b0), "r"(b1));
}

__device__ __forceinline__ void ldsm_x4(uint32_t& r0, uint32_t& r1,
                                        uint32_t& r2, uint32_t& r3,
                                        uint32_t addr) {
    asm volatile("ldmatrix.sync.aligned.m8n8.x4.shared.b16 {%0,%1,%2,%3}, [%4];"
        : "=r"(r0), "=r"(r1), "=r"(r2), "=r"(r3) : "r"(addr));
}

__device__ __forceinline__ void ldsm_x4_t(uint32_t& r0, uint32_t& r1,
                                          uint32_t& r2, uint32_t& r3,
                                          uint32_t addr) {
    asm volatile("ldmatrix.sync.aligned.m8n8.x4.trans.shared.b16 {%0,%1,%2,%3}, [%4];"
        : "=r"(r0), "=r"(r1), "=r"(r2), "=r"(r3) : "r"(addr));
}

__device__ __forceinline__ void cp16(void* smem_dst, const void* gmem_src) {
    uint32_t s = (uint32_t)__cvta_generic_to_shared(smem_dst);
    asm volatile("cp.async.cg.shared.global [%0], [%1], 16;" :: "r"(s), "l"(gmem_src));
}

// ---------------------------------------------------------------------------
// All 4 weight matrices fp32 -> bf16 in one kernel (float4 granularity).
// Segments: wqa 16384, wqb 49152, wpa 16384, wpb 16384 float4s (total 98304).
// ---------------------------------------------------------------------------
__global__ void cvt_weights_kernel(const float* __restrict__ a0, bf16* __restrict__ o0,
                                   const float* __restrict__ a1, bf16* __restrict__ o1,
                                   const float* __restrict__ a2, bf16* __restrict__ o2,
                                   const float* __restrict__ a3, bf16* __restrict__ o3)
{
    int i = blockIdx.x * blockDim.x + threadIdx.x;
    const float* src; bf16* dst; int off;
    if (i < 16384)      { src = a0; dst = o0; off = i; }
    else if (i < 65536) { src = a1; dst = o1; off = i - 16384; }
    else if (i < 81920) { src = a2; dst = o2; off = i - 65536; }
    else if (i < 98304) { src = a3; dst = o3; off = i - 81920; }
    else return;
    float4 v = ((const float4*)src)[off];
    uint2 u;
    u.x = pack_bf16(v.x, v.y);
    u.y = pack_bf16(v.z, v.w);
    ((uint2*)dst)[off] = u;
}

// ---------------------------------------------------------------------------
// Tensor-core "rank" GEMM: out[M,64] = gelu(A[M,1024] @ W[1024,64] + bias)
// FP32IN=1: A is fp32, loaded via LDG + in-register cvt + STS (reg double
// buffered). FP32IN=0: A is bf16 via cp.async. W always bf16 via cp.async.
// Block: 32 rows, 128 thr (4 warps). 2-stage pipeline, k-tile 64.
// ---------------------------------------------------------------------------
template<int FP32IN>
__global__ void __launch_bounds__(128)
gemm_rank_tc(const void* __restrict__ Av, const bf16* __restrict__ W,
             const float* __restrict__ bias, bf16* __restrict__ out)
{
    __shared__ __align__(16) bf16 As[2][32][72];
    __shared__ __align__(16) bf16 Ws[2][64][72];

    const int m0   = blockIdx.x * 32;
    const int tid  = threadIdx.x;
    const int w    = tid >> 5;
    const int lane = tid & 31;
    const int g    = lane >> 2;
    const int tig  = lane & 3;
    const int l8   = lane & 7;
    const int seg  = lane >> 3;

    const uint32_t offA = (uint32_t)(((seg & 1) * 8 + l8) * 144 + ((seg >> 1) & 1) * 16);
    const uint32_t asa = (uint32_t)__cvta_generic_to_shared(&As[0][0][0]) + offA
                       + (uint32_t)((w & 1) * 16 * 144);
    const uint32_t wsa = (uint32_t)__cvta_generic_to_shared(&Ws[0][0][0]) + offA
                       + (uint32_t)((w >> 1) * 64);   // 32 cols * 2B

    const bf16*  Ab = (const bf16*)Av;
    const float* Af = (const float*)Av;

    // bf16 loader indices (2 cp16/thread)
    const int ar0 = tid >> 3, ac = (tid & 7) * 8;
    const int ar1 = (tid + 128) >> 3;

    const int NT = C_ / 64;   // 16

    float4 ra[4];   // fp32 path register buffer (tile 32x64 fp32, 4 float4/thr)

    auto loadW = [&](int kt) {
        const int s = kt & 1, k0 = kt * 64;
        #pragma unroll
        for (int rep = 0; rep < 4; rep++) {
            int idx = tid + 128 * rep;
            int r = idx >> 3, c = (idx & 7) * 8;
            cp16(&Ws[s][r][c], W + (size_t)(k0 + r) * R_ + c);
        }
        asm volatile("cp.async.commit_group;");
    };
    auto loadA_bf = [&](int kt) {
        const int s = kt & 1, k0 = kt * 64;
        cp16(&As[s][ar0][ac], Ab + (size_t)(m0 + ar0) * C_ + k0 + ac);
        cp16(&As[s][ar1][ac], Ab + (size_t)(m0 + ar1) * C_ + k0 + ac);
    };
    auto loadA_f32 = [&](int kt) {
        const int k0 = kt * 64;
        #pragma unroll
        for (int rep = 0; rep < 4; rep++) {
            int idx = tid + 128 * rep;
            int r = idx >> 4, c4 = idx & 15;
            ra[rep] = *(const float4*)(Af + (size_t)(m0 + r) * C_ + k0 + 4 * c4);
        }
    };
    auto stsA_f32 = [&](int s) {
        #pragma unroll
        for (int rep = 0; rep < 4; rep++) {
            int idx = tid + 128 * rep;
            int r = idx >> 4, c4 = idx & 15;
            uint2 u;
            u.x = pack_bf16(ra[rep].x, ra[rep].y);
            u.y = pack_bf16(ra[rep].z, ra[rep].w);
            *(uint2*)&As[s][r][4 * c4] = u;
        }
    };

    // prologue
    if (FP32IN) {
        loadA_f32(0);
        loadW(0);
        stsA_f32(0);
        loadA_f32(1);
        loadW(1);
        asm volatile("cp.async.wait_group 1;");
    } else {
        loadA_bf(0);
        loadW(0);
        loadA_bf(1);
        loadW(1);
        asm volatile("cp.async.wait_group 1;");
    }
    __syncthreads();

    float c4a[4][4];
    #pragma unroll
    for (int n = 0; n < 4; n++)
        #pragma unroll
        for (int j = 0; j < 4; j++) c4a[n][j] = 0.0f;

    for (int kt = 0; kt < NT; kt++) {
        const uint32_t ab = asa + (uint32_t)((kt & 1) * 32 * 144);
        const uint32_t wb = wsa + (uint32_t)((kt & 1) * 64 * 144);
        #pragma unroll
        for (int ks = 0; ks < 4; ks++) {
            uint32_t a[4];
            ldsm_x4(a[0], a[1], a[2], a[3], ab + (uint32_t)(ks * 32));
            #pragma unroll
            for (int ntp = 0; ntp < 2; ntp++) {
                uint32_t b00, b01, b10, b11;
                ldsm_x4_t(b00, b01, b10, b11,
                          wb + (uint32_t)(ks * 16 * 144 + ntp * 32));
                mma16816(c4a[2 * ntp],     a, b00, b01);
                mma16816(c4a[2 * ntp + 1], a, b10, b11);
            }
        }
        if (kt + 1 < NT) {
            __syncthreads();   // done computing kt everywhere; stage (kt+1)&1 free
            if (FP32IN) {
                stsA_f32((kt + 1) & 1);
                if (kt + 2 < NT) { loadA_f32(kt + 2); loadW(kt + 2); }
            } else {
                if (kt + 2 < NT) { loadA_bf(kt + 2); loadW(kt + 2); }
            }
            if (kt + 2 < NT) asm volatile("cp.async.wait_group 1;");
            else             asm volatile("cp.async.wait_group 0;");
            __syncthreads();
        }
    }

    // epilogue: bias + gelu + bf16 store
    const int row0 = m0 + (w & 1) * 16 + g;
    const int cb   = (w >> 1) * 32;
    #pragma unroll
    for (int n = 0; n < 4; n++) {
        int col = cb + 8 * n + 2 * tig;
        float v0 = c4a[n][0], v1 = c4a[n][1], v2 = c4a[n][2], v3 = c4a[n][3];
        if (bias) {
            float b0 = bias[col], b1 = bias[col + 1];
            v0 += b0; v1 += b1; v2 += b0; v3 += b1;
        }
        v0 = gelu_exact(v0); v1 = gelu_exact(v1);
        v2 = gelu_exact(v2); v3 = gelu_exact(v3);
        *(uint32_t*)(out + (size_t)row0 * R_ + col)       = pack_bf16(v0, v1);
        *(uint32_t*)(out + (size_t)(row0 + 8) * R_ + col) = pack_bf16(v2, v3);
    }
}

// ---------------------------------------------------------------------------
// Tensor-core "expand" GEMM: out[M,Nout] = A[M,64] @ W[64,Nout] + bias
// ---------------------------------------------------------------------------
template<int BF16OUT>
__global__ void __launch_bounds__(128)
gemm_expand_tc(const bf16* __restrict__ A, const bf16* __restrict__ W,
               const float* __restrict__ bias, void* __restrict__ outv,
               int Nout)
{
    __shared__ __align__(16) bf16 As[64][72];
    __shared__ __align__(16) bf16 Ws[64][136];

    const int n0   = blockIdx.x * 128;
    const int m0   = blockIdx.y * 64;
    const int tid  = threadIdx.x;
    const int w    = tid >> 5;
    const int lane = tid & 31;
    const int g    = lane >> 2;
    const int tig  = lane & 3;
    const int l8   = lane & 7;
    const int seg  = lane >> 3;

    #pragma unroll
    for (int rep = 0; rep < 4; rep++) {
        int idx = tid + 128 * rep;
        int r = idx >> 3, c = (idx & 7) * 8;
        *(uint4*)&As[r][c] = *(const uint4*)(A + (size_t)(m0 + r) * R_ + c);
    }
    #pragma unroll
    for (int rep = 0; rep < 8; rep++) {
        int idx = tid + 128 * rep;
        int r = idx >> 4, c = (idx & 15) * 8;
        *(uint4*)&Ws[r][c] = *(const uint4*)(W + (size_t)r * Nout + n0 + c);
    }
    __syncthreads();

    const uint32_t offA144 = (uint32_t)(((seg & 1) * 8 + l8) * 144 + ((seg >> 1) & 1) * 16);
    const uint32_t offA272 = (uint32_t)(((seg & 1) * 8 + l8) * 272 + ((seg >> 1) & 1) * 16);
    const uint32_t asa = (uint32_t)__cvta_generic_to_shared(&As[0][0]) + offA144
                       + (uint32_t)(w * 16 * 144);
    const uint32_t wsa = (uint32_t)__cvta_generic_to_shared(&Ws[0][0]) + offA272;

    uint32_t qf[4][4];
    #pragma unroll
    for (int ks = 0; ks < 4; ks++)
        ldsm_x4(qf[ks][0], qf[ks][1], qf[ks][2], qf[ks][3],
                asa + (uint32_t)(ks * 32));

    float c4[16][4];
    #pragma unroll
    for (int n = 0; n < 16; n++)
        #pragma unroll
        for (int j = 0; j < 4; j++) c4[n][j] = 0.0f;

    #pragma unroll
    for (int ks = 0; ks < 4; ks++) {
        #pragma unroll
        for (int ntp = 0; ntp < 8; ntp++) {
            uint32_t b00, b01, b10, b11;
            ldsm_x4_t(b00, b01, b10, b11,
                      wsa + (uint32_t)(ks * 16 * 272 + ntp * 32));
            mma16816(c4[2 * ntp],     qf[ks], b00, b01);
            mma16816(c4[2 * ntp + 1], qf[ks], b10, b11);
        }
    }

    const int row0 = m0 + 16 * w + g;
    #pragma unroll
    for (int n = 0; n < 16; n++) {
        int col = n0 + 8 * n + 2 * tig;
        float v0 = c4[n][0], v1 = c4[n][1], v2 = c4[n][2], v3 = c4[n][3];
        if (bias) {
            float b0 = bias[col], b1 = bias[col + 1];
            v0 += b0; v1 += b1; v2 += b0; v3 += b1;
        }
        if (BF16OUT) {
            bf16* out = (bf16*)outv;
            *(uint32_t*)(out + (size_t)row0 * Nout + col)       = pack_bf16(v0, v1);
            *(uint32_t*)(out + (size_t)(row0 + 8) * Nout + col) = pack_bf16(v2, v3);
        } else {
            float* out = (float*)outv;
            *(float2*)(out + (size_t)row0 * Nout + col)       = make_float2(v0, v1);
            *(float2*)(out + (size_t)(row0 + 8) * Nout + col) = make_float2(v2, v3);
        }
    }
}

// ---------------------------------------------------------------------------
// Flash attention v3: Br=128, Bc=64, 8 warps (256 thr), dynamic smem 54KB.
// Q pre-scaled by 0.125 (exact in bf16). 2-stage cp.async K/V pipeline.
// Grid (16 q-tiles, 32 bh). Halves K/V L2 traffic vs Br=64.
// ---------------------------------------------------------------------------
#define ROWB 144
#define KVSTAGE (64 * 144)
#define FLASH_SMEM (128 * 144 + 2 * KVSTAGE + 2 * KVSTAGE)   // 55296 B

__global__ void __launch_bounds__(256)
flash_mma_kernel(const bf16* __restrict__ qkv, bf16* __restrict__ attn_out)
{
    extern __shared__ __align__(16) char dsm[];
    bf16* Qs = (bf16*)dsm;                         // [128][72]
    char* Kc = dsm + 128 * ROWB;                   // [2][64][72]
    char* Vc = Kc + 2 * KVSTAGE;                   // [2][64][72]

    const int qt   = blockIdx.x;     // 0..15
    const int bh   = blockIdx.y;
    const int b    = bh >> 4;
    const int h    = bh & 15;
    const int tid  = threadIdx.x;
    const int w    = tid >> 5;       // 0..7
    const int lane = tid & 31;
    const int g    = lane >> 2;
    const int tig  = lane & 3;
    const int l8   = lane & 7;
    const int seg  = lane >> 3;

    const uint32_t offA = (uint32_t)(((seg & 1) * 8 + l8) * ROWB + ((seg >> 1) & 1) * 16);
    const uint32_t offB = (uint32_t)((((seg >> 1) & 1) * 8 + l8) * ROWB + (seg & 1) * 16);

    const uint32_t qsa = (uint32_t)__cvta_generic_to_shared(Qs) + offA;
    const uint32_t ksa = (uint32_t)__cvta_generic_to_shared(Kc) + offB;
    const uint32_t vsa = (uint32_t)__cvta_generic_to_shared(Vc) + offA;

    const bf16* qbase = qkv + (size_t)(b * N_ + qt * 128) * QKV3_ + h * DH_;
    const bf16* kbase = qkv + (size_t)(b * N_) * QKV3_ + C_ + h * DH_;
    const bf16* vbase = kbase + C_;

    // Load Q tile (128x64), pre-scaled by 0.125 (exact bf16 scaling)
    const uint32_t s125 = 0x3E003E00u;   // bf16x2 {0.125, 0.125}
    #pragma unroll
    for (int rep = 0; rep < 4; rep++) {
        int idx = tid + 256 * rep;
        int r = idx >> 3, c = (idx & 7) * 8;
        uint4 v = *(const uint4*)(qbase + (size_t)r * QKV3_ + c);
        v.x = mulbf2(v.x, s125); v.y = mulbf2(v.y, s125);
        v.z = mulbf2(v.z, s125); v.w = mulbf2(v.w, s125);
        *(uint4*)(Qs + r * 72 + c) = v;
    }

    // Prologue: K/V stage 0
    #pragma unroll
    for (int rep = 0; rep < 2; rep++) {
        int idx = tid + 256 * rep;
        int r = idx >> 3, c = (idx & 7) * 8;
        size_t go = (size_t)r * QKV3_ + c;
        cp16(Kc + r * ROWB + c * 2, kbase + go);
        cp16(Vc + r * ROWB + c * 2, vbase + go);
    }
    asm volatile("cp.async.commit_group;");

    __syncthreads();
    uint32_t qf[4][4];
    #pragma unroll
    for (int ks = 0; ks < 4; ks++)
        ldsm_x4(qf[ks][0], qf[ks][1], qf[ks][2], qf[ks][3],
                qsa + (uint32_t)(w * 16 * ROWB + ks * 32));

    float o[8][4];
    #pragma unroll
    for (int n = 0; n < 8; n++)
        #pragma unroll
        for (int j = 0; j < 4; j++) o[n][j] = 0.0f;
    float m0 = -1e30f, m1 = -1e30f, l0 = 0.0f, l1 = 0.0f;

    const int T = N_ / 64;   // 32
    for (int t = 0; t < T; t++) {
        if (t + 1 < T) {
            const int s = (t + 1) & 1;
            #pragma unroll
            for (int rep = 0; rep < 2; rep++) {
                int idx = tid + 256 * rep;
                int r = idx >> 3, c = (idx & 7) * 8;
                size_t go = (size_t)((t + 1) * 64 + r) * QKV3_ + c;
                cp16(Kc + s * KVSTAGE + r * ROWB + c * 2, kbase + go);
                cp16(Vc + s * KVSTAGE + r * ROWB + c * 2, vbase + go);
            }
            asm volatile("cp.async.commit_group;");
            asm volatile("cp.async.wait_group 1;");
        } else {
            asm volatile("cp.async.wait_group 0;");
        }
        __syncthreads();

        const uint32_t kb = ksa + (uint32_t)((t & 1) * KVSTAGE);
        const uint32_t vb = vsa + (uint32_t)((t & 1) * KVSTAGE);

        // S = Q K^T  (Q pre-scaled)
        float s[8][4];
        #pragma unroll
        for (int n = 0; n < 8; n++)
            #pragma unroll
            for (int j = 0; j < 4; j++) s[n][j] = 0.0f;

        #pragma unroll
        for (int ks = 0; ks < 4; ks++) {
            #pragma unroll
            for (int ntp = 0; ntp < 4; ntp++) {
                uint32_t b00, b01, b10, b11;
                ldsm_x4(b00, b01, b10, b11,
                        kb + (uint32_t)(ntp * 16 * ROWB + ks * 32));
                mma16816(s[2 * ntp],     qf[ks], b00, b01);
                mma16816(s[2 * ntp + 1], qf[ks], b10, b11);
            }
        }

        // Online softmax
        float mx0 = -1e30f, mx1 = -1e30f;
        #pragma unroll
        for (int n = 0; n < 8; n++) {
            mx0 = fmaxf(mx0, fmaxf(s[n][0], s[n][1]));
            mx1 = fmaxf(mx1, fmaxf(s[n][2], s[n][3]));
        }
        mx0 = fmaxf(mx0, __shfl_xor_sync(0xffffffffu, mx0, 1));
        mx0 = fmaxf(mx0, __shfl_xor_sync(0xffffffffu, mx0, 2));
        mx1 = fmaxf(mx1, __shfl_xor_sync(0xffffffffu, mx1, 1));
        mx1 = fmaxf(mx1, __shfl_xor_sync(0xffffffffu, mx1, 2));

        float mn0 = fmaxf(m0, mx0), mn1 = fmaxf(m1, mx1);
        float cr0 = __expf(m0 - mn0), cr1 = __expf(m1 - mn1);
        m0 = mn0; m1 = mn1;

        float rs0 = 0.0f, rs1 = 0.0f;
        #pragma unroll
        for (int n = 0; n < 8; n++) {
            s[n][0] = __expf(s[n][0] - mn0);
            s[n][1] = __expf(s[n][1] - mn0);
            s[n][2] = __expf(s[n][2] - mn1);
            s[n][3] = __expf(s[n][3] - mn1);
            rs0 += s[n][0] + s[n][1];
            rs1 += s[n][2] + s[n][3];
        }
        rs0 += __shfl_xor_sync(0xffffffffu, rs0, 1);
        rs0 += __shfl_xor_sync(0xffffffffu, rs0, 2);
        rs1 += __shfl_xor_sync(0xffffffffu, rs1, 1);
        rs1 += __shfl_xor_sync(0xffffffffu, rs1, 2);
        l0 = l0 * cr0 + rs0;
        l1 = l1 * cr1 + rs1;
        #pragma unroll
        for (int n = 0; n < 8; n++) {
            o[n][0] *= cr0; o[n][1] *= cr0; o[n][2] *= cr1; o[n][3] *= cr1;
        }

        // O += P V
        #pragma unroll
        for (int ks = 0; ks < 4; ks++) {
            uint32_t a[4];
            a[0] = pack_bf16(s[2 * ks    ][0], s[2 * ks    ][1]);
            a[1] = pack_bf16(s[2 * ks    ][2], s[2 * ks    ][3]);
            a[2] = pack_bf16(s[2 * ks + 1][0], s[2 * ks + 1][1]);
            a[3] = pack_bf16(s[2 * ks + 1][2], s[2 * ks + 1][3]);
            #pragma unroll
            for (int ntp = 0; ntp < 4; ntp++) {
                uint32_t b00, b01, b10, b11;
                ldsm_x4_t(b00, b01, b10, b11,
                          vb + (uint32_t)(ks * 16 * ROWB + ntp * 32));
                mma16816(o[2 * ntp],     a, b00, b01);
                mma16816(o[2 * ntp + 1], a, b10, b11);
            }
        }
        __syncthreads();
    }

    // Epilogue: bf16 output
    float inv0 = 1.0f / l0, inv1 = 1.0f / l1;
    int row0 = b * N_ + qt * 128 + 16 * w + g;
    bf16* out0 = attn_out + (size_t)row0 * C_ + h * DH_;
    bf16* out1 = out0 + (size_t)8 * C_;
    #pragma unroll
    for (int n = 0; n < 8; n++) {
        *(uint32_t*)(out0 + 8 * n + 2 * tig) = pack_bf16(o[n][0] * inv0, o[n][1] * inv0);
        *(uint32_t*)(out1 + 8 * n + 2 * tig) = pack_bf16(o[n][2] * inv1, o[n][3] * inv1);
    }
}

// ---------------------------------------------------------------------------
extern "C" void kernel_launch(void* const* d_in, const int* in_sizes, int n_in,
                              void* d_out, int out_size)
{
    const float* x        = (const float*)d_in[0];
    const float* w_qkv_a  = (const float*)d_in[1];
    const float* w_qkv_b  = (const float*)d_in[2];
    const float* w_proj_a = (const float*)d_in[3];
    const float* b_proj_a = (const float*)d_in[4];
    const float* w_proj_b = (const float*)d_in[5];
    const float* b_proj_b = (const float*)d_in[6];
    float* out = (float*)d_out;

    bf16 *wqa, *wqb, *wpa, *wpb, *h1, *qkv, *attn, *h2;
    cudaGetSymbolAddress((void**)&wqa,  g_wqa);
    cudaGetSymbolAddress((void**)&wqb,  g_wqb);
    cudaGetSymbolAddress((void**)&wpa,  g_wpa);
    cudaGetSymbolAddress((void**)&wpb,  g_wpb);
    cudaGetSymbolAddress((void**)&h1,   g_h1);
    cudaGetSymbolAddress((void**)&qkv,  g_qkv);
    cudaGetSymbolAddress((void**)&attn, g_attn);
    cudaGetSymbolAddress((void**)&h2,   g_h2);

    cudaFuncSetAttribute(flash_mma_kernel,
                         cudaFuncAttributeMaxDynamicSharedMemorySize, FLASH_SMEM);

    // 0) weights -> bf16 (single kernel)
    cvt_weights_kernel<<<384, 256>>>(w_qkv_a, wqa, w_qkv_b, wqb,
                                     w_proj_a, wpa, w_proj_b, wpb);

    // 1) h1 = gelu(x @ w_qkv_a)  (x fp32, converted inline)
    gemm_rank_tc<1><<<M_ / 32, 128>>>(x, wqa, nullptr, h1);
    // 2) qkv = h1 @ w_qkv_b  (bf16 out)
    gemm_expand_tc<1><<<dim3(QKV3_ / 128, M_ / 64), 128>>>(h1, wqb, nullptr, qkv, QKV3_);
    // 3) attention (Br=128 flash)
    flash_mma_kernel<<<dim3(N_ / 128, B_ * H_), 256, FLASH_SMEM>>>(qkv, attn);
    // 4) h2 = gelu(attn @ w_proj_a + b_proj_a)
    gemm_rank_tc<0><<<M_ / 32, 128>>>(attn, wpa, b_proj_a, h2);
    // 5) out = h2 @ w_proj_b + b_proj_b  (fp32 out)
    gemm_expand_tc<0><<<dim3(C_ / 128, M_ / 64), 128>>>(h2, wpb, b_proj_b, out, C_);
}